// round 2
// baseline (speedup 1.0000x reference)
#include <cuda_runtime.h>

typedef unsigned long long ull;

// ---- packed f32x2 helpers ----
__device__ __forceinline__ ull pk2(float lo, float hi) {
    ull r; asm("mov.b64 %0, {%1, %2};" : "=l"(r) : "f"(lo), "f"(hi)); return r;
}
__device__ __forceinline__ ull bc2(float v) { return pk2(v, v); }
__device__ __forceinline__ void upk2(ull r, float& lo, float& hi) {
    asm("mov.b64 {%0, %1}, %2;" : "=f"(lo), "=f"(hi) : "l"(r));
}
__device__ __forceinline__ ull fma2(ull a, ull b, ull c) {
    ull d; asm("fma.rn.f32x2 %0, %1, %2, %3;" : "=l"(d) : "l"(a), "l"(b), "l"(c)); return d;
}
__device__ __forceinline__ ull add2(ull a, ull b) {
    ull d; asm("add.rn.f32x2 %0, %1, %2;" : "=l"(d) : "l"(a), "l"(b)); return d;
}
__device__ __forceinline__ ull mul2(ull a, ull b) {
    ull d; asm("mul.rn.f32x2 %0, %1, %2;" : "=l"(d) : "l"(a), "l"(b)); return d;
}
__device__ __forceinline__ float ex2a(float x) {
    float y; asm("ex2.approx.f32 %0, %1;" : "=f"(y) : "f"(x)); return y;
}
__device__ __forceinline__ float rcpa(float x) {
    float y; asm("rcp.approx.f32 %0, %1;" : "=f"(y) : "f"(x)); return y;
}

// Shapes: b=4, c=16, m=8, h=w=64, O=64.
// Block: 512 threads, tile = 2 rows x 8 cols (4 superpixels).
// Thread: jh = t&1 (j-half), sp = (t>>1)&3 (superpixel), o = t>>3.
//
// Smem layout (floats):
//   qs  [0,16448)  : q[i][o*16+pix], i-stride 1028 (bank-padded)
//   xs  [16448,..) : x[ch][m*16+pix], ch-stride 132
//   res [18560,..) : 0.125*sum_m x, [i*16+pix]
//   wqs [18816,..) : wq * 0.125*log2(e), [o*8+m]
//   wkp [19328,..) : ull pairs, [g*33 + j2*8 + m], rows (8g+2j2, 8g+2j2+1)
//   wvp [19856,..) : same for wv
#define QS_I 1028
#define XS_CH 132
#define SMEM_FLOATS 20384
#define SMEM_BYTES (SMEM_FLOATS * 4)

__global__ __launch_bounds__(512, 1) void adapt_attn(
    const float* __restrict__ x,
    const float* __restrict__ wq,
    const float* __restrict__ wk,
    const float* __restrict__ wv,
    float* __restrict__ out)
{
    extern __shared__ __align__(16) float smem[];
    float* qs  = smem;
    float* xs  = smem + 16448;
    float* res = smem + 18560;
    float* wqs = smem + 18816;
    ull*   wkp = (ull*)(smem + 19328);
    ull*   wvp = (ull*)(smem + 19856);

    const int t   = threadIdx.x;
    const int lwg = blockIdx.x;   // 0..7
    const int lh  = blockIdx.y;   // 0..31
    const int b   = blockIdx.z;   // 0..3
    const int hh0 = 2 * lh, ww0 = 8 * lwg;

    // ---- stage x tile (2048 floats): pix = sp*4 + (hhi*2 + colbit) ----
    {
        int q4  = t & 1;
        int hhi = (t >> 1) & 1;
        int m   = (t >> 2) & 7;
        int ch  = t >> 5;
        const float4 v = *reinterpret_cast<const float4*>(
            x + ((b * 16 + ch) * 8 + m) * 4096 + (hh0 + hhi) * 64 + ww0 + 4 * q4);
        float* dst = xs + ch * XS_CH + m * 16 + 8 * q4 + 2 * hhi;
        *reinterpret_cast<ull*>(dst)     = pk2(v.x, v.y);   // sp=2q4
        *reinterpret_cast<ull*>(dst + 4) = pk2(v.z, v.w);   // sp=2q4+1
    }
    // ---- stage weights ----
    wqs[t] = wq[t] * 0.18033688011112042f;   // 0.125 * log2(e)
    {
        int m = t & 7, j2 = (t >> 3) & 3, g = (t >> 5) & 7;
        if (t < 256)
            wkp[g * 33 + j2 * 8 + m] =
                pk2(wk[(8 * g + 2 * j2) * 8 + m], wk[(8 * g + 2 * j2 + 1) * 8 + m]);
        else
            wvp[g * 33 + j2 * 8 + m] =
                pk2(wv[(8 * g + 2 * j2) * 8 + m], wv[(8 * g + 2 * j2 + 1) * 8 + m]);
    }
    __syncthreads();

    // ---- res = 0.125 * sum_m x (independent of o) ----
    if (t < 256) {
        int i = t >> 4, pix = t & 15;
        const float* xr = xs + i * XS_CH + pix;
        float s = 0.f;
#pragma unroll
        for (int m = 0; m < 8; ++m) s += xr[m * 16];
        res[i * 16 + pix] = 0.125f * s;
    }

    // ---- cooperative q compute: q[i][o][pix] (computed once, not per jh) ----
    {
        int oo = t >> 3, sub = t & 7;
        ull wrb[8];
#pragma unroll
        for (int m = 0; m < 8; ++m) wrb[m] = bc2(wqs[oo * 8 + m]);
#pragma unroll
        for (int ii = 0; ii < 2; ++ii) {
            int i = sub + 8 * ii;
            ull acc[8];
#pragma unroll
            for (int p = 0; p < 8; ++p) acc[p] = 0ull;
            const float* xr = xs + i * XS_CH;
#pragma unroll
            for (int m = 0; m < 8; ++m) {
                const float4* r = reinterpret_cast<const float4*>(xr + m * 16);
                float4 a = r[0], bb = r[1], cc = r[2], dd = r[3];
                acc[0] = fma2(wrb[m], pk2(a.x, a.y), acc[0]);
                acc[1] = fma2(wrb[m], pk2(a.z, a.w), acc[1]);
                acc[2] = fma2(wrb[m], pk2(bb.x, bb.y), acc[2]);
                acc[3] = fma2(wrb[m], pk2(bb.z, bb.w), acc[3]);
                acc[4] = fma2(wrb[m], pk2(cc.x, cc.y), acc[4]);
                acc[5] = fma2(wrb[m], pk2(cc.z, cc.w), acc[5]);
                acc[6] = fma2(wrb[m], pk2(dd.x, dd.y), acc[6]);
                acc[7] = fma2(wrb[m], pk2(dd.z, dd.w), acc[7]);
            }
            ull* qdst = reinterpret_cast<ull*>(qs + i * QS_I + oo * 16);
#pragma unroll
            for (int p = 0; p < 8; ++p) qdst[p] = acc[p];
        }
    }

    // ---- per-thread k/v for its (o, jh) half: 8 local j as 4 pairs ----
    const int jh = t & 1;
    const int sp = (t >> 1) & 3;
    const int o  = t >> 3;
    const int ck = o >> 2;
    const int g  = (o & 3) * 2 + jh;     // wk/wv rows 8g .. 8g+7

    ull kq[4][4], vq[4][4];              // [j2][p], packed over (2j2, 2j2+1)
#pragma unroll
    for (int j2 = 0; j2 < 4; ++j2)
#pragma unroll
        for (int p = 0; p < 4; ++p) { kq[j2][p] = 0ull; vq[j2][p] = 0ull; }
    {
        const float* xck = xs + ck * XS_CH;
        const ull* wkg = wkp + g * 33;
        const ull* wvg = wvp + g * 33;
#pragma unroll
        for (int m = 0; m < 8; ++m) {
            float4 xv = *reinterpret_cast<const float4*>(xck + m * 16 + sp * 4);
            ull xb0 = bc2(xv.x), xb1 = bc2(xv.y), xb2 = bc2(xv.z), xb3 = bc2(xv.w);
#pragma unroll
            for (int j2 = 0; j2 < 4; ++j2) {
                ull wkv = wkg[j2 * 8 + m];
                kq[j2][0] = fma2(wkv, xb0, kq[j2][0]);
                kq[j2][1] = fma2(wkv, xb1, kq[j2][1]);
                kq[j2][2] = fma2(wkv, xb2, kq[j2][2]);
                kq[j2][3] = fma2(wkv, xb3, kq[j2][3]);
                ull wvv = wvg[j2 * 8 + m];
                vq[j2][0] = fma2(wvv, xb0, vq[j2][0]);
                vq[j2][1] = fma2(wvv, xb1, vq[j2][1]);
                vq[j2][2] = fma2(wvv, xb2, vq[j2][2]);
                vq[j2][3] = fma2(wvv, xb3, vq[j2][3]);
            }
        }
    }
    __syncthreads();

    const float* qso  = qs + o * 16 + sp * 4;
    const ull*   resp = reinterpret_cast<const ull*>(res + sp * 4 + jh * 2);
    float* op = out + ((b * 16) * 64 + o) * 4096 + (hh0 + jh) * 64 + ww0 + 2 * sp;

#pragma unroll 1
    for (int i = 0; i < 16; ++i) {
        float4 qv = *reinterpret_cast<const float4*>(qso + i * QS_I);
        ull qb0 = bc2(qv.x), qb1 = bc2(qv.y), qb2 = bc2(qv.z), qb3 = bc2(qv.w);

        // att (already scaled by 0.125*log2e via wq) -> e = 2^att  (no max: |att| << 30)
        ull ep[4];
#pragma unroll
        for (int j2 = 0; j2 < 4; ++j2) {
            ull at = mul2(qb0, kq[j2][0]);
            at = fma2(qb1, kq[j2][1], at);
            at = fma2(qb2, kq[j2][2], at);
            at = fma2(qb3, kq[j2][3], at);
            float alo, ahi; upk2(at, alo, ahi);
            ep[j2] = pk2(ex2a(alo), ex2a(ahi));
        }

        // softmax denominator across both j-halves (butterfly over jh bit)
        ull s2 = add2(add2(ep[0], ep[1]), add2(ep[2], ep[3]));
        float slo, shi; upk2(s2, slo, shi);
        float fs = slo + shi;
        fs += __shfl_xor_sync(0xffffffffu, fs, 1);
        float inv = rcpa(fs);

        // partial out over this j-half: oa[p] = sum_j2 ep[j2] * vq[j2][p]
        ull oa[4];
#pragma unroll
        for (int p = 0; p < 4; ++p) {
            ull a = mul2(ep[0], vq[0][p]);
            a = fma2(ep[1], vq[1][p], a);
            a = fma2(ep[2], vq[2][p], a);
            a = fma2(ep[3], vq[3][p], a);
            oa[p] = a;
        }
        float f0, f1, f2, f3, g0, g1, g2, g3;
        upk2(oa[0], f0, g0); upk2(oa[1], f1, g1);
        upk2(oa[2], f2, g2); upk2(oa[3], f3, g3);
        ull mineA = pk2(f0 + g0, f1 + g1);   // pixels (p0,p1) = row hh0
        ull mineB = pk2(f2 + g2, f3 + g3);   // pixels (p2,p3) = row hh0+1

        // exchange halves: jh0 finalizes row A, jh1 row B
        ull keep = jh ? mineB : mineA;
        ull send = jh ? mineA : mineB;
        ull recv = __shfl_xor_sync(0xffffffffu, send, 1);
        ull tot  = add2(keep, recv);

        ull fin = fma2(tot, bc2(inv), resp[i * 8]);
        *reinterpret_cast<ull*>(op) = fin;
        op += 64 * 4096;
    }
}

extern "C" void kernel_launch(void* const* d_in, const int* in_sizes, int n_in,
                              void* d_out, int out_size) {
    const float* x  = (const float*)d_in[0];
    const float* wq = (const float*)d_in[1];
    const float* wk = (const float*)d_in[2];
    const float* wv = (const float*)d_in[3];
    // d_in[4] (w_p): positional term is constant over the softmax axis -> cancels exactly.
    static int attr_set = 0;
    if (!attr_set) {
        cudaFuncSetAttribute(adapt_attn, cudaFuncAttributeMaxDynamicSharedMemorySize,
                             SMEM_BYTES);
        attr_set = 1;
    }
    dim3 grid(8, 32, 4);
    adapt_attn<<<grid, 512, SMEM_BYTES>>>(x, wq, wk, wv, (float*)d_out);
}